// round 10
// baseline (speedup 1.0000x reference)
#include <cuda_runtime.h>
#include <math.h>

#define B_   4
#define C_   256
#define H_   32
#define W_   32
#define N_   1024
#define NH_  8
#define HC_  32
#define NG_  4
#define GC_  64
#define BG_  16
#define SCALE_ 0.17677669529663687f   /* 32^-0.5 */
#define EPS_  1e-5f

// ---- scratch (device globals; no allocations allowed) ----
__device__ float g_q  [B_*C_*N_];
__device__ float g_pos[BG_*N_*2];
__device__ float g_xs [B_*C_*N_];
__device__ float g_k  [B_*C_*N_];
__device__ float g_v  [B_*C_*N_];
__device__ float g_o  [B_*C_*N_];

typedef unsigned long long ull;

// ---- packed f32x2 helpers ----
__device__ __forceinline__ void fma2(ull& d, ull a, ull b) {
    asm("fma.rn.f32x2 %0, %1, %2, %0;" : "+l"(d) : "l"(a), "l"(b));
}
__device__ __forceinline__ void mul2(ull& d, ull a) {
    asm("mul.rn.f32x2 %0, %0, %1;" : "+l"(d) : "l"(a));
}
__device__ __forceinline__ float2 u2f(ull v) {
    float2 r; asm("mov.b64 {%0, %1}, %2;" : "=f"(r.x), "=f"(r.y) : "l"(v)); return r;
}
__device__ __forceinline__ ull fdup(float x) {
    ull r; asm("mov.b64 %0, {%1, %1};" : "=l"(r) : "f"(x)); return r;
}

// Fast exp on the FMA pipe (avoids MUFU throughput wall).
__device__ __forceinline__ float fexp(float x) {
    float t = fmaxf(x * 1.4426950408889634f, -126.0f);
    float n = rintf(t);
    float f = t - n;
    float p =             1.3333558146e-3f;
    p = fmaf(p, f, 9.6181291794e-3f);
    p = fmaf(p, f, 5.5504108625e-2f);
    p = fmaf(p, f, 2.4022650696e-1f);
    p = fmaf(p, f, 6.9314718056e-1f);
    p = fmaf(p, f, 1.0f);
    return p * __int_as_float(((int)n + 127) << 23);
}

// ============================================================
// Projection GEMM (R3 scalar 4x4 + register double-buffer prefetch)
// ============================================================
__device__ __forceinline__ void gemm_tile(
        const float* __restrict__ Wt, const float* __restrict__ bias,
        const float* __restrict__ Xb, float* __restrict__ Yb,
        int p0, int o0, float (*Ws)[68], float (*Xs)[68]) {
    int tid = threadIdx.x;
    int tx = tid & 15, ty = tid >> 4;
    int lc = tx << 2;
    float acc[4][4] = {};
    const float* wp = Wt + (size_t)(o0 + lc) * C_ + ty;

    float w0 = wp[0], w1 = wp[C_], w2 = wp[2 * C_], w3 = wp[3 * C_];
    float4 x4 = *(const float4*)&Xb[(size_t)ty * N_ + p0 + lc];

    for (int kt = 0; kt < C_; kt += 16) {
        Ws[ty][lc + 0] = w0; Ws[ty][lc + 1] = w1;
        Ws[ty][lc + 2] = w2; Ws[ty][lc + 3] = w3;
        *(float4*)&Xs[ty][lc] = x4;
        __syncthreads();
        int nk = kt + 16;
        if (nk < C_) {
            w0 = wp[nk]; w1 = wp[C_ + nk]; w2 = wp[2 * C_ + nk]; w3 = wp[3 * C_ + nk];
            x4 = *(const float4*)&Xb[(size_t)(nk + ty) * N_ + p0 + lc];
        }
#pragma unroll
        for (int kk = 0; kk < 16; kk++) {
            float4 wv = *(const float4*)&Ws[kk][ty << 2];
            float4 xv = *(const float4*)&Xs[kk][tx << 2];
            acc[0][0] = fmaf(wv.x, xv.x, acc[0][0]);
            acc[0][1] = fmaf(wv.x, xv.y, acc[0][1]);
            acc[0][2] = fmaf(wv.x, xv.z, acc[0][2]);
            acc[0][3] = fmaf(wv.x, xv.w, acc[0][3]);
            acc[1][0] = fmaf(wv.y, xv.x, acc[1][0]);
            acc[1][1] = fmaf(wv.y, xv.y, acc[1][1]);
            acc[1][2] = fmaf(wv.y, xv.z, acc[1][2]);
            acc[1][3] = fmaf(wv.y, xv.w, acc[1][3]);
            acc[2][0] = fmaf(wv.z, xv.x, acc[2][0]);
            acc[2][1] = fmaf(wv.z, xv.y, acc[2][1]);
            acc[2][2] = fmaf(wv.z, xv.z, acc[2][2]);
            acc[2][3] = fmaf(wv.z, xv.w, acc[2][3]);
            acc[3][0] = fmaf(wv.w, xv.x, acc[3][0]);
            acc[3][1] = fmaf(wv.w, xv.y, acc[3][1]);
            acc[3][2] = fmaf(wv.w, xv.z, acc[3][2]);
            acc[3][3] = fmaf(wv.w, xv.w, acc[3][3]);
        }
        __syncthreads();
    }
#pragma unroll
    for (int i = 0; i < 4; i++) {
        int o = o0 + (ty << 2) + i;
        float bs = bias[o];
        float4 r = make_float4(acc[i][0] + bs, acc[i][1] + bs,
                               acc[i][2] + bs, acc[i][3] + bs);
        *(float4*)&Yb[(size_t)o * N_ + p0 + lc] = r;
    }
}

__global__ __launch_bounds__(256) void gemm_proj(
        const float* __restrict__ Wt, const float* __restrict__ bias,
        const float* __restrict__ X, float* __restrict__ Y) {
    __shared__ float Ws[16][68], Xs[16][68];
    int b = blockIdx.z;
    gemm_tile(Wt, bias, X + (size_t)b * C_ * N_, Y + (size_t)b * C_ * N_,
              blockIdx.x << 6, blockIdx.y << 6, Ws, Xs);
}

__global__ __launch_bounds__(256) void gemm_kv(
        const float* __restrict__ Wk, const float* __restrict__ bk,
        const float* __restrict__ Wv, const float* __restrict__ bv,
        const float* __restrict__ X, float* __restrict__ Yk, float* __restrict__ Yv) {
    __shared__ float Ws[16][68], Xs[16][68];
    int z = blockIdx.z;
    int b = z >> 1, sel = z & 1;
    gemm_tile(sel ? Wv : Wk, sel ? bv : bk,
              X + (size_t)b * C_ * N_, (sel ? Yv : Yk) + (size_t)b * C_ * N_,
              blockIdx.x << 6, blockIdx.y << 6, Ws, Xs);
}

// ============================================================
// Offset network: depthwise 3x3 -> LN -> GELU -> pointwise(2)
// ============================================================
__global__ void offset_kernel(const float* __restrict__ dw_w, const float* __restrict__ dw_b,
                              const float* __restrict__ ln_w, const float* __restrict__ ln_b,
                              const float* __restrict__ pw_w) {
    int idx = blockIdx.x * blockDim.x + threadIdx.x;   // bg*N + p
    if (idx >= BG_ * N_) return;
    int bg = idx >> 10, p = idx & (N_ - 1);
    int h = p >> 5, w = p & 31;
    int b = bg >> 2, g = bg & 3;
    const float* qbase = g_q + (size_t)b * C_ * N_ + (size_t)g * GC_ * N_;

    float x[GC_];
    float s1 = 0.f;
#pragma unroll
    for (int c = 0; c < GC_; c++) {
        const float* qc = qbase + c * N_;
        float t = dw_b[c];
#pragma unroll
        for (int dy = 0; dy < 3; dy++) {
            int hh = h + dy - 1;
            if (hh < 0 || hh >= H_) continue;
#pragma unroll
            for (int dx = 0; dx < 3; dx++) {
                int ww = w + dx - 1;
                if (ww < 0 || ww >= W_) continue;
                t += dw_w[c * 9 + dy * 3 + dx] * qc[hh * W_ + ww];
            }
        }
        x[c] = t; s1 += t;
    }
    float mu = s1 * (1.f / GC_);
    float s2 = 0.f;
#pragma unroll
    for (int c = 0; c < GC_; c++) { float d = x[c] - mu; s2 += d * d; }
    float rinv = rsqrtf(s2 * (1.f / GC_) + EPS_);
    float off0 = 0.f, off1 = 0.f;
#pragma unroll
    for (int c = 0; c < GC_; c++) {
        float xn  = (x[c] - mu) * rinv * ln_w[c] + ln_b[c];
        float gel = 0.5f * xn * (1.f + erff(xn * 0.7071067811865476f));
        off0 += pw_w[c] * gel;          // y
        off1 += pw_w[GC_ + c] * gel;    // x
    }
    const float rng = 4.0f / 31.0f;
    float py = tanhf(off0) * rng + ((0.5f + (float)h) / 31.f) * 2.f - 1.f;
    float px = tanhf(off1) * rng + ((0.5f + (float)w) / 31.f) * 2.f - 1.f;
    g_pos[idx * 2 + 0] = py;
    g_pos[idx * 2 + 1] = px;
}

// ============================================================
// Deformable bilinear sampling of kv features
// ============================================================
__global__ void sample_kernel(const float* __restrict__ kv) {
    int blk = blockIdx.x;                 // bg*N + p
    int c = threadIdx.x;
    int bg = blk >> 10, p = blk & (N_ - 1);
    int b = bg >> 2, g = bg & 3;
    float py = g_pos[blk * 2 + 0], px = g_pos[blk * 2 + 1];
    float ix = (px + 1.f) * 15.5f;
    float iy = (py + 1.f) * 15.5f;
    float x0f = floorf(ix), y0f = floorf(iy);
    float wx1 = ix - x0f, wx0 = 1.f - wx1;
    float wy1 = iy - y0f, wy0 = 1.f - wy1;
    int x0 = (int)x0f, y0 = (int)y0f;
    const float* src = kv + ((size_t)b * C_ + g * GC_ + c) * N_;
    float acc = 0.f;
#pragma unroll
    for (int cy = 0; cy < 2; cy++) {
        int yy = y0 + cy;
        if (yy < 0 || yy >= H_) continue;
        float wy = cy ? wy1 : wy0;
#pragma unroll
        for (int cx = 0; cx < 2; cx++) {
            int xx = x0 + cx;
            if (xx < 0 || xx >= W_) continue;
            acc += wy * (cx ? wx1 : wx0) * src[yy * W_ + xx];
        }
    }
    g_xs[((size_t)b * C_ + g * GC_ + c) * N_ + p] = acc;
}

// ============================================================
// Fused flash attention.
// QK: FFMA2 packed over m (q naturally paired; k dup'd in regs).
// PV: FFMA2 packed over n (both operands naturally paired).
// Online softmax WITH max subtraction; per-thread partial sums.
// RPE bias: fp32 69x69 zero-padded smem table (pad 3 each side;
// coordinate range y0 in [-3,64]), constant-fraction bilinear.
// ============================================================
#define FL_QS 0
#define FL_KS 8704
#define FL_VS 17408
#define FL_PS 26112
#define FL_TB 43520            /* 69*69 floats = 19044 B (pad to 19072) */
#define FL_PY 62592
#define FL_PX 62848
#define FL_SMEM 63104

__global__ __launch_bounds__(256) void flash_kernel(const float* __restrict__ rpe) {
    extern __shared__ char sm_[];
    float* qs  = (float*)(sm_ + FL_QS);    // [32][68]  (pre-scaled q)
    float* ks  = (float*)(sm_ + FL_KS);    // [32][68]
    float* vs  = (float*)(sm_ + FL_VS);    // [32][68]
    float* ps  = (float*)(sm_ + FL_PS);    // [64][68]
    float* tb  = (float*)(sm_ + FL_TB);    // [69][69] zero-padded
    float* pyn = (float*)(sm_ + FL_PY);    // 64
    float* pxn = (float*)(sm_ + FL_PX);    // 64

    int tid = threadIdx.x;
    int tx = tid & 15, ty = tid >> 4;
    int bh = blockIdx.y, b = bh >> 3, hd = bh & 7;
    int m0 = blockIdx.x << 6;

    const float* qb = g_q + (size_t)(b * C_ + hd * HC_) * N_;
    const float* kb = g_k + (size_t)(b * C_ + hd * HC_) * N_;
    const float* vb = g_v + (size_t)(b * C_ + hd * HC_) * N_;
    int bg = b * NG_ + (hd >> 1);
    const float* tsrc = rpe + hd * 3969;

    // zero padded table, load q tile (scaled)
    for (int i = tid; i < 69 * 69; i += 256) tb[i] = 0.f;
    for (int i = tid; i < 512; i += 256) {
        int c = i >> 4, col = (i & 15) << 2;
        float4 v = *(const float4*)&qb[(size_t)c * N_ + m0 + col];
        v.x *= SCALE_; v.y *= SCALE_; v.z *= SCALE_; v.w *= SCALE_;
        *(float4*)&qs[c * 68 + col] = v;
    }
    __syncthreads();
    // table interior at [3][3]
    for (int i = tid; i < 3969; i += 256) {
        int y = i / 63, x = i - y * 63;
        tb[(y + 3) * 69 + x + 3] = tsrc[i];
    }

    int moff[4];
#pragma unroll
    for (int i = 0; i < 4; i++) {
        int m = m0 + (ty << 2) + i;
        moff[i] = (m >> 5) * 69 + (m & 31);
    }

    float runm[4] = {-1e30f, -1e30f, -1e30f, -1e30f};
    float rsum[4] = {};
    ull o20[4] = {}, o21[4] = {};   // packed n-pair partials, channels tx / tx+16

    for (int nt = 0; nt < 16; nt++) {
        int n0 = nt << 6;
        __syncthreads();   // prev PV done (iter 0: table fill done)
        for (int i = tid; i < 512; i += 256) {
            int c = i >> 4, col = (i & 15) << 2;
            *(float4*)&ks[c * 68 + col] = *(const float4*)&kb[(size_t)c * N_ + n0 + col];
            *(float4*)&vs[c * 68 + col] = *(const float4*)&vb[(size_t)c * N_ + n0 + col];
        }
        if (tid < 64) {
            pyn[tid] = 15.5f - 15.5f * g_pos[((size_t)bg * N_ + n0 + tid) * 2 + 0];
            pxn[tid] = 15.5f - 15.5f * g_pos[((size_t)bg * N_ + n0 + tid) * 2 + 1];
        }
        __syncthreads();

        // ---- S = Q^T K: FFMA2 packed over m ----
        // acc2[j][p]: j = n-idx 0..3, p = m-pair (m0,m1)/(m2,m3)
        ull acc2[4][2] = {};
#pragma unroll
        for (int c = 0; c < 32; c++) {
            ulonglong2 qp = *(const ulonglong2*)&qs[c * 68 + (ty << 2)];
            float4 kv4 = *(const float4*)&ks[c * 68 + (tx << 2)];
            ull kd0 = fdup(kv4.x), kd1 = fdup(kv4.y);
            ull kd2 = fdup(kv4.z), kd3 = fdup(kv4.w);
            fma2(acc2[0][0], kd0, qp.x); fma2(acc2[0][1], kd0, qp.y);
            fma2(acc2[1][0], kd1, qp.x); fma2(acc2[1][1], kd1, qp.y);
            fma2(acc2[2][0], kd2, qp.x); fma2(acc2[2][1], kd2, qp.y);
            fma2(acc2[3][0], kd3, qp.x); fma2(acc2[3][1], kd3, qp.y);
        }
        float sv[4][4];
#pragma unroll
        for (int j = 0; j < 4; j++) {
            float2 a = u2f(acc2[j][0]), c2 = u2f(acc2[j][1]);
            sv[0][j] = a.x; sv[1][j] = a.y; sv[2][j] = c2.x; sv[3][j] = c2.y;
        }

        // ---- + rpe bias (fractions constant per n; pad-3 table) ----
#pragma unroll
        for (int j = 0; j < 4; j++) {
            int nn = (tx << 2) + j;
            float biy = pyn[nn], bix = pxn[nn];
            float fy = floorf(biy), fx = floorf(bix);
            float wy1 = biy - fy, wx1 = bix - fx;
            float wy0 = 1.f - wy1, wx0 = 1.f - wx1;
            int idxb = ((int)fy + 3) * 69 + (int)fx + 3;
            float w00 = wy0 * wx0, w01 = wy0 * wx1;
            float w10 = wy1 * wx0, w11 = wy1 * wx1;
#pragma unroll
            for (int i = 0; i < 4; i++) {
                int idx = idxb + moff[i];
                sv[i][j] += w00 * tb[idx] + w01 * tb[idx + 1]
                          + w10 * tb[idx + 69] + w11 * tb[idx + 70];
            }
        }

        // ---- online softmax: max via shfl; sums stay per-thread ----
#pragma unroll
        for (int i = 0; i < 4; i++) {
            float tm = fmaxf(fmaxf(sv[i][0], sv[i][1]), fmaxf(sv[i][2], sv[i][3]));
#pragma unroll
            for (int off = 1; off < 16; off <<= 1)
                tm = fmaxf(tm, __shfl_xor_sync(0xffffffffu, tm, off));
            float nm = fmaxf(runm[i], tm);
            float corr = fexp(runm[i] - nm);
            runm[i] = nm;
            float p0 = fexp(sv[i][0] - nm);
            float p1 = fexp(sv[i][1] - nm);
            float p2 = fexp(sv[i][2] - nm);
            float p3 = fexp(sv[i][3] - nm);
            rsum[i] = rsum[i] * corr + ((p0 + p1) + (p2 + p3));
            ull cd = fdup(corr);
            mul2(o20[i], cd); mul2(o21[i], cd);
            *(float4*)&ps[((ty << 2) + i) * 68 + (tx << 2)] = make_float4(p0, p1, p2, p3);
        }
        __syncwarp();

        // ---- O += P V: FFMA2 packed over n ----
#pragma unroll
        for (int n4 = 0; n4 < 16; n4++) {
            ulonglong2 v0 = *(const ulonglong2*)&vs[tx * 68 + (n4 << 2)];
            ulonglong2 v1 = *(const ulonglong2*)&vs[(tx + 16) * 68 + (n4 << 2)];
#pragma unroll
            for (int i = 0; i < 4; i++) {
                ulonglong2 pp = *(const ulonglong2*)&ps[((ty << 2) + i) * 68 + (n4 << 2)];
                fma2(o20[i], pp.x, v0.x); fma2(o20[i], pp.y, v0.y);
                fma2(o21[i], pp.x, v1.x); fma2(o21[i], pp.y, v1.y);
            }
        }
    }

    // final row-sum reduction (once) and normalize
    float inv[4];
#pragma unroll
    for (int i = 0; i < 4; i++) {
        float rs = rsum[i];
#pragma unroll
        for (int off = 1; off < 16; off <<= 1)
            rs += __shfl_xor_sync(0xffffffffu, rs, off);
        inv[i] = 1.f / rs;
    }
    __syncthreads();
#pragma unroll
    for (int i = 0; i < 4; i++) {
        float2 a = u2f(o20[i]), c2 = u2f(o21[i]);
        ps[((ty << 2) + i) * 68 + tx]      = (a.x + a.y) * inv[i];
        ps[((ty << 2) + i) * 68 + tx + 16] = (c2.x + c2.y) * inv[i];
    }
    __syncthreads();
    float* ob = g_o + (size_t)(b * C_ + hd * HC_) * N_;
    for (int i = tid; i < 2048; i += 256) {
        int c = i >> 6, m = i & 63;
        ob[(size_t)c * N_ + m0 + m] = ps[m * 68 + c];
    }
}

// ============================================================
extern "C" void kernel_launch(void* const* d_in, const int* in_sizes, int n_in,
                              void* d_out, int out_size) {
    const float* q_feat = (const float*)d_in[0];
    const float* kv_feat = (const float*)d_in[1];
    const float* Wq = (const float*)d_in[2];
    const float* bq = (const float*)d_in[3];
    const float* Wk = (const float*)d_in[4];
    const float* bk = (const float*)d_in[5];
    const float* Wv = (const float*)d_in[6];
    const float* bv = (const float*)d_in[7];
    const float* Wo = (const float*)d_in[8];
    const float* bo = (const float*)d_in[9];
    const float* dw_w = (const float*)d_in[10];
    const float* dw_b = (const float*)d_in[11];
    const float* ln_w = (const float*)d_in[12];
    const float* ln_b = (const float*)d_in[13];
    const float* pw_w = (const float*)d_in[14];
    const float* rpe  = (const float*)d_in[15];
    float* out = (float*)d_out;

    float *gq, *gxs, *gk, *gv, *go;
    cudaGetSymbolAddress((void**)&gq,  g_q);
    cudaGetSymbolAddress((void**)&gxs, g_xs);
    cudaGetSymbolAddress((void**)&gk,  g_k);
    cudaGetSymbolAddress((void**)&gv,  g_v);
    cudaGetSymbolAddress((void**)&go,  g_o);

    static int smem_set = 0;
    if (!smem_set) {
        cudaFuncSetAttribute(flash_kernel,
                             cudaFuncAttributeMaxDynamicSharedMemorySize, FL_SMEM);
        smem_set = 1;
    }

    dim3 gemm_grid(N_ / 64, C_ / 64, B_);
    dim3 kv_grid(N_ / 64, C_ / 64, B_ * 2);

    gemm_proj<<<gemm_grid, 256>>>(Wq, bq, q_feat, gq);
    offset_kernel<<<(BG_ * N_ + 255) / 256, 256>>>(dw_w, dw_b, ln_w, ln_b, pw_w);
    sample_kernel<<<BG_ * N_, GC_>>>(kv_feat);
    gemm_kv<<<kv_grid, 256>>>(Wk, bk, Wv, bv, gxs, gk, gv);
    flash_kernel<<<dim3(N_ / 64, B_ * NH_), 256, FL_SMEM>>>(rpe);
    gemm_proj<<<gemm_grid, 256>>>(Wo, bo, go, out);
}

// round 11
// speedup vs baseline: 1.1691x; 1.1691x over previous
#include <cuda_runtime.h>
#include <math.h>

#define B_   4
#define C_   256
#define H_   32
#define W_   32
#define N_   1024
#define NH_  8
#define HC_  32
#define NG_  4
#define GC_  64
#define BG_  16
#define SCALE_ 0.17677669529663687f   /* 32^-0.5 */
#define EPS_  1e-5f

// ---- scratch (device globals; no allocations allowed) ----
__device__ float g_q  [B_*C_*N_];
__device__ float g_pos[BG_*N_*2];
__device__ float g_xs [B_*C_*N_];
__device__ float g_k  [B_*C_*N_];
__device__ float g_v  [B_*C_*N_];
__device__ float g_o  [B_*C_*N_];

typedef unsigned long long ull;

// ---- packed f32x2 helpers ----
__device__ __forceinline__ void fma2(ull& d, ull a, ull b) {
    asm("fma.rn.f32x2 %0, %1, %2, %0;" : "+l"(d) : "l"(a), "l"(b));
}
__device__ __forceinline__ void mul2(ull& d, ull a) {
    asm("mul.rn.f32x2 %0, %0, %1;" : "+l"(d) : "l"(a));
}
__device__ __forceinline__ float2 u2f(ull v) {
    float2 r; asm("mov.b64 {%0, %1}, %2;" : "=f"(r.x), "=f"(r.y) : "l"(v)); return r;
}
__device__ __forceinline__ ull fdup(float x) {
    ull r; asm("mov.b64 %0, {%1, %1};" : "=l"(r) : "f"(x)); return r;
}

// ---- tf32 mma helpers ----
__device__ __forceinline__ unsigned cvt_tf32(float x) {
    unsigned r; asm("cvt.rna.tf32.f32 %0, %1;" : "=r"(r) : "f"(x)); return r;
}
__device__ __forceinline__ void mma_tf32(float* d, const unsigned* a, const unsigned* b) {
    asm("mma.sync.aligned.m16n8k8.row.col.f32.tf32.tf32.f32 "
        "{%0,%1,%2,%3}, {%4,%5,%6,%7}, {%8,%9}, {%0,%1,%2,%3};"
        : "+f"(d[0]), "+f"(d[1]), "+f"(d[2]), "+f"(d[3])
        : "r"(a[0]), "r"(a[1]), "r"(a[2]), "r"(a[3]), "r"(b[0]), "r"(b[1]));
}

// Fast exp on the FMA pipe (avoids MUFU throughput wall).
__device__ __forceinline__ float fexp(float x) {
    float t = fmaxf(x * 1.4426950408889634f, -126.0f);
    float n = rintf(t);
    float f = t - n;
    float p =             1.3333558146e-3f;
    p = fmaf(p, f, 9.6181291794e-3f);
    p = fmaf(p, f, 5.5504108625e-2f);
    p = fmaf(p, f, 2.4022650696e-1f);
    p = fmaf(p, f, 6.9314718056e-1f);
    p = fmaf(p, f, 1.0f);
    return p * __int_as_float(((int)n + 127) << 23);
}

// ============================================================
// Projection GEMM via tf32 tensor-core mma.sync.
// Y[o,p] = sum_i W[o,i]*X[i,p] + bias[o]
// Block: 64(o) x 64(p), 128 threads = 4 warps, warp tile 32x32.
// Per k8 step each warp does 2x4 = 8 m16n8k8 mmas.
// ============================================================
__device__ __forceinline__ void gemm_tile_tf32(
        const float* __restrict__ Wt, const float* __restrict__ bias,
        const float* __restrict__ Xb, float* __restrict__ Yb,
        int p0, int o0, float (*Ws)[72], float (*Xs)[72]) {
    int tid = threadIdx.x;
    int lane = tid & 31, wid = tid >> 5;
    int gid = lane >> 2, tig = lane & 3;
    int wm0 = (wid >> 1) << 5;   // warp o-offset (0/32)
    int wn0 = (wid & 1) << 5;    // warp p-offset (0/32)

    float acc[2][4][4] = {};

    for (int kt = 0; kt < C_; kt += 16) {
        // stage W^T slab: Ws[k][o] = W[o0+o][kt+k]
        {
            int o = tid >> 1, kq = (tid & 1) << 3;
            const float* wp = &Wt[(size_t)(o0 + o) * C_ + kt + kq];
            float4 wa = *(const float4*)wp;
            float4 wb = *(const float4*)(wp + 4);
            Ws[kq + 0][o] = wa.x; Ws[kq + 1][o] = wa.y;
            Ws[kq + 2][o] = wa.z; Ws[kq + 3][o] = wa.w;
            Ws[kq + 4][o] = wb.x; Ws[kq + 5][o] = wb.y;
            Ws[kq + 6][o] = wb.z; Ws[kq + 7][o] = wb.w;
        }
        // stage X slab: Xs[k][p]
#pragma unroll
        for (int it = 0; it < 2; it++) {
            int i4 = tid + (it << 7);
            int k = i4 >> 4, p = (i4 & 15) << 2;
            *(float4*)&Xs[k][p] = *(const float4*)&Xb[(size_t)(kt + k) * N_ + p0 + p];
        }
        __syncthreads();

#pragma unroll
        for (int ks = 0; ks < 16; ks += 8) {
            unsigned afr[2][4], bfr[4][2];
#pragma unroll
            for (int mi = 0; mi < 2; mi++) {
                int r = wm0 + (mi << 4) + gid;
                afr[mi][0] = cvt_tf32(Ws[ks + tig][r]);
                afr[mi][1] = cvt_tf32(Ws[ks + tig][r + 8]);
                afr[mi][2] = cvt_tf32(Ws[ks + tig + 4][r]);
                afr[mi][3] = cvt_tf32(Ws[ks + tig + 4][r + 8]);
            }
#pragma unroll
            for (int ni = 0; ni < 4; ni++) {
                int cc = wn0 + (ni << 3) + gid;
                bfr[ni][0] = cvt_tf32(Xs[ks + tig][cc]);
                bfr[ni][1] = cvt_tf32(Xs[ks + tig + 4][cc]);
            }
#pragma unroll
            for (int mi = 0; mi < 2; mi++)
#pragma unroll
                for (int ni = 0; ni < 4; ni++)
                    mma_tf32(acc[mi][ni], afr[mi], bfr[ni]);
        }
        __syncthreads();
    }

    // epilogue: c0 (r, 2*tig), c1 (r, 2*tig+1), c2 (r+8, 2*tig), c3 (r+8, +1)
#pragma unroll
    for (int mi = 0; mi < 2; mi++) {
        int r = wm0 + (mi << 4) + gid;
        float bs0 = bias[o0 + r], bs1 = bias[o0 + r + 8];
#pragma unroll
        for (int ni = 0; ni < 4; ni++) {
            int cb = p0 + wn0 + (ni << 3) + (tig << 1);
            float* y0 = &Yb[(size_t)(o0 + r) * N_ + cb];
            float* y1 = &Yb[(size_t)(o0 + r + 8) * N_ + cb];
            *(float2*)y0 = make_float2(acc[mi][ni][0] + bs0, acc[mi][ni][1] + bs0);
            *(float2*)y1 = make_float2(acc[mi][ni][2] + bs1, acc[mi][ni][3] + bs1);
        }
    }
}

__global__ __launch_bounds__(128) void gemm_proj(
        const float* __restrict__ Wt, const float* __restrict__ bias,
        const float* __restrict__ X, float* __restrict__ Y) {
    __shared__ float Ws[16][72], Xs[16][72];
    int b = blockIdx.z;
    gemm_tile_tf32(Wt, bias, X + (size_t)b * C_ * N_, Y + (size_t)b * C_ * N_,
                   blockIdx.x << 6, blockIdx.y << 6, Ws, Xs);
}

__global__ __launch_bounds__(128) void gemm_kv(
        const float* __restrict__ Wk, const float* __restrict__ bk,
        const float* __restrict__ Wv, const float* __restrict__ bv,
        const float* __restrict__ X, float* __restrict__ Yk, float* __restrict__ Yv) {
    __shared__ float Ws[16][72], Xs[16][72];
    int z = blockIdx.z;
    int b = z >> 1, sel = z & 1;
    gemm_tile_tf32(sel ? Wv : Wk, sel ? bv : bk,
                   X + (size_t)b * C_ * N_, (sel ? Yv : Yk) + (size_t)b * C_ * N_,
                   blockIdx.x << 6, blockIdx.y << 6, Ws, Xs);
}

// ============================================================
// Offset network: depthwise 3x3 -> LN -> GELU -> pointwise(2)
// ============================================================
__global__ void offset_kernel(const float* __restrict__ dw_w, const float* __restrict__ dw_b,
                              const float* __restrict__ ln_w, const float* __restrict__ ln_b,
                              const float* __restrict__ pw_w) {
    int idx = blockIdx.x * blockDim.x + threadIdx.x;   // bg*N + p
    if (idx >= BG_ * N_) return;
    int bg = idx >> 10, p = idx & (N_ - 1);
    int h = p >> 5, w = p & 31;
    int b = bg >> 2, g = bg & 3;
    const float* qbase = g_q + (size_t)b * C_ * N_ + (size_t)g * GC_ * N_;

    float x[GC_];
    float s1 = 0.f;
#pragma unroll
    for (int c = 0; c < GC_; c++) {
        const float* qc = qbase + c * N_;
        float t = dw_b[c];
#pragma unroll
        for (int dy = 0; dy < 3; dy++) {
            int hh = h + dy - 1;
            if (hh < 0 || hh >= H_) continue;
#pragma unroll
            for (int dx = 0; dx < 3; dx++) {
                int ww = w + dx - 1;
                if (ww < 0 || ww >= W_) continue;
                t += dw_w[c * 9 + dy * 3 + dx] * qc[hh * W_ + ww];
            }
        }
        x[c] = t; s1 += t;
    }
    float mu = s1 * (1.f / GC_);
    float s2 = 0.f;
#pragma unroll
    for (int c = 0; c < GC_; c++) { float d = x[c] - mu; s2 += d * d; }
    float rinv = rsqrtf(s2 * (1.f / GC_) + EPS_);
    float off0 = 0.f, off1 = 0.f;
#pragma unroll
    for (int c = 0; c < GC_; c++) {
        float xn  = (x[c] - mu) * rinv * ln_w[c] + ln_b[c];
        float gel = 0.5f * xn * (1.f + erff(xn * 0.7071067811865476f));
        off0 += pw_w[c] * gel;          // y
        off1 += pw_w[GC_ + c] * gel;    // x
    }
    const float rng = 4.0f / 31.0f;
    float py = tanhf(off0) * rng + ((0.5f + (float)h) / 31.f) * 2.f - 1.f;
    float px = tanhf(off1) * rng + ((0.5f + (float)w) / 31.f) * 2.f - 1.f;
    g_pos[idx * 2 + 0] = py;
    g_pos[idx * 2 + 1] = px;
}

// ============================================================
// Deformable bilinear sampling of kv features
// ============================================================
__global__ void sample_kernel(const float* __restrict__ kv) {
    int blk = blockIdx.x;                 // bg*N + p
    int c = threadIdx.x;
    int bg = blk >> 10, p = blk & (N_ - 1);
    int b = bg >> 2, g = bg & 3;
    float py = g_pos[blk * 2 + 0], px = g_pos[blk * 2 + 1];
    float ix = (px + 1.f) * 15.5f;
    float iy = (py + 1.f) * 15.5f;
    float x0f = floorf(ix), y0f = floorf(iy);
    float wx1 = ix - x0f, wx0 = 1.f - wx1;
    float wy1 = iy - y0f, wy0 = 1.f - wy1;
    int x0 = (int)x0f, y0 = (int)y0f;
    const float* src = kv + ((size_t)b * C_ + g * GC_ + c) * N_;
    float acc = 0.f;
#pragma unroll
    for (int cy = 0; cy < 2; cy++) {
        int yy = y0 + cy;
        if (yy < 0 || yy >= H_) continue;
        float wy = cy ? wy1 : wy0;
#pragma unroll
        for (int cx = 0; cx < 2; cx++) {
            int xx = x0 + cx;
            if (xx < 0 || xx >= W_) continue;
            acc += wy * (cx ? wx1 : wx0) * src[yy * W_ + xx];
        }
    }
    g_xs[((size_t)b * C_ + g * GC_ + c) * N_ + p] = acc;
}

// ============================================================
// Fused flash attention (unchanged from R10 winner).
// ============================================================
#define FL_QS 0
#define FL_KS 8704
#define FL_VS 17408
#define FL_PS 26112
#define FL_TB 43520            /* 69*69 floats = 19044 B (pad to 19072) */
#define FL_PY 62592
#define FL_PX 62848
#define FL_SMEM 63104

__global__ __launch_bounds__(256) void flash_kernel(const float* __restrict__ rpe) {
    extern __shared__ char sm_[];
    float* qs  = (float*)(sm_ + FL_QS);    // [32][68]  (pre-scaled q)
    float* ks  = (float*)(sm_ + FL_KS);    // [32][68]
    float* vs  = (float*)(sm_ + FL_VS);    // [32][68]
    float* ps  = (float*)(sm_ + FL_PS);    // [64][68]
    float* tb  = (float*)(sm_ + FL_TB);    // [69][69] zero-padded
    float* pyn = (float*)(sm_ + FL_PY);    // 64
    float* pxn = (float*)(sm_ + FL_PX);    // 64

    int tid = threadIdx.x;
    int tx = tid & 15, ty = tid >> 4;
    int bh = blockIdx.y, b = bh >> 3, hd = bh & 7;
    int m0 = blockIdx.x << 6;

    const float* qb = g_q + (size_t)(b * C_ + hd * HC_) * N_;
    const float* kb = g_k + (size_t)(b * C_ + hd * HC_) * N_;
    const float* vb = g_v + (size_t)(b * C_ + hd * HC_) * N_;
    int bg = b * NG_ + (hd >> 1);
    const float* tsrc = rpe + hd * 3969;

    for (int i = tid; i < 69 * 69; i += 256) tb[i] = 0.f;
    for (int i = tid; i < 512; i += 256) {
        int c = i >> 4, col = (i & 15) << 2;
        float4 v = *(const float4*)&qb[(size_t)c * N_ + m0 + col];
        v.x *= SCALE_; v.y *= SCALE_; v.z *= SCALE_; v.w *= SCALE_;
        *(float4*)&qs[c * 68 + col] = v;
    }
    __syncthreads();
    for (int i = tid; i < 3969; i += 256) {
        int y = i / 63, x = i - y * 63;
        tb[(y + 3) * 69 + x + 3] = tsrc[i];
    }

    int moff[4];
#pragma unroll
    for (int i = 0; i < 4; i++) {
        int m = m0 + (ty << 2) + i;
        moff[i] = (m >> 5) * 69 + (m & 31);
    }

    float runm[4] = {-1e30f, -1e30f, -1e30f, -1e30f};
    float rsum[4] = {};
    ull o20[4] = {}, o21[4] = {};

    for (int nt = 0; nt < 16; nt++) {
        int n0 = nt << 6;
        __syncthreads();
        for (int i = tid; i < 512; i += 256) {
            int c = i >> 4, col = (i & 15) << 2;
            *(float4*)&ks[c * 68 + col] = *(const float4*)&kb[(size_t)c * N_ + n0 + col];
            *(float4*)&vs[c * 68 + col] = *(const float4*)&vb[(size_t)c * N_ + n0 + col];
        }
        if (tid < 64) {
            pyn[tid] = 15.5f - 15.5f * g_pos[((size_t)bg * N_ + n0 + tid) * 2 + 0];
            pxn[tid] = 15.5f - 15.5f * g_pos[((size_t)bg * N_ + n0 + tid) * 2 + 1];
        }
        __syncthreads();

        ull acc2[4][2] = {};
#pragma unroll
        for (int c = 0; c < 32; c++) {
            ulonglong2 qp = *(const ulonglong2*)&qs[c * 68 + (ty << 2)];
            float4 kv4 = *(const float4*)&ks[c * 68 + (tx << 2)];
            ull kd0 = fdup(kv4.x), kd1 = fdup(kv4.y);
            ull kd2 = fdup(kv4.z), kd3 = fdup(kv4.w);
            fma2(acc2[0][0], kd0, qp.x); fma2(acc2[0][1], kd0, qp.y);
            fma2(acc2[1][0], kd1, qp.x); fma2(acc2[1][1], kd1, qp.y);
            fma2(acc2[2][0], kd2, qp.x); fma2(acc2[2][1], kd2, qp.y);
            fma2(acc2[3][0], kd3, qp.x); fma2(acc2[3][1], kd3, qp.y);
        }
        float sv[4][4];
#pragma unroll
        for (int j = 0; j < 4; j++) {
            float2 a = u2f(acc2[j][0]), c2 = u2f(acc2[j][1]);
            sv[0][j] = a.x; sv[1][j] = a.y; sv[2][j] = c2.x; sv[3][j] = c2.y;
        }

#pragma unroll
        for (int j = 0; j < 4; j++) {
            int nn = (tx << 2) + j;
            float biy = pyn[nn], bix = pxn[nn];
            float fy = floorf(biy), fx = floorf(bix);
            float wy1 = biy - fy, wx1 = bix - fx;
            float wy0 = 1.f - wy1, wx0 = 1.f - wx1;
            int idxb = ((int)fy + 3) * 69 + (int)fx + 3;
            float w00 = wy0 * wx0, w01 = wy0 * wx1;
            float w10 = wy1 * wx0, w11 = wy1 * wx1;
#pragma unroll
            for (int i = 0; i < 4; i++) {
                int idx = idxb + moff[i];
                sv[i][j] += w00 * tb[idx] + w01 * tb[idx + 1]
                          + w10 * tb[idx + 69] + w11 * tb[idx + 70];
            }
        }

#pragma unroll
        for (int i = 0; i < 4; i++) {
            float tm = fmaxf(fmaxf(sv[i][0], sv[i][1]), fmaxf(sv[i][2], sv[i][3]));
#pragma unroll
            for (int off = 1; off < 16; off <<= 1)
                tm = fmaxf(tm, __shfl_xor_sync(0xffffffffu, tm, off));
            float nm = fmaxf(runm[i], tm);
            float corr = fexp(runm[i] - nm);
            runm[i] = nm;
            float p0 = fexp(sv[i][0] - nm);
            float p1 = fexp(sv[i][1] - nm);
            float p2 = fexp(sv[i][2] - nm);
            float p3 = fexp(sv[i][3] - nm);
            rsum[i] = rsum[i] * corr + ((p0 + p1) + (p2 + p3));
            ull cd = fdup(corr);
            mul2(o20[i], cd); mul2(o21[i], cd);
            *(float4*)&ps[((ty << 2) + i) * 68 + (tx << 2)] = make_float4(p0, p1, p2, p3);
        }
        __syncwarp();

#pragma unroll
        for (int n4 = 0; n4 < 16; n4++) {
            ulonglong2 v0 = *(const ulonglong2*)&vs[tx * 68 + (n4 << 2)];
            ulonglong2 v1 = *(const ulonglong2*)&vs[(tx + 16) * 68 + (n4 << 2)];
#pragma unroll
            for (int i = 0; i < 4; i++) {
                ulonglong2 pp = *(const ulonglong2*)&ps[((ty << 2) + i) * 68 + (n4 << 2)];
                fma2(o20[i], pp.x, v0.x); fma2(o20[i], pp.y, v0.y);
                fma2(o21[i], pp.x, v1.x); fma2(o21[i], pp.y, v1.y);
            }
        }
    }

    float inv[4];
#pragma unroll
    for (int i = 0; i < 4; i++) {
        float rs = rsum[i];
#pragma unroll
        for (int off = 1; off < 16; off <<= 1)
            rs += __shfl_xor_sync(0xffffffffu, rs, off);
        inv[i] = 1.f / rs;
    }
    __syncthreads();
#pragma unroll
    for (int i = 0; i < 4; i++) {
        float2 a = u2f(o20[i]), c2 = u2f(o21[i]);
        ps[((ty << 2) + i) * 68 + tx]      = (a.x + a.y) * inv[i];
        ps[((ty << 2) + i) * 68 + tx + 16] = (c2.x + c2.y) * inv[i];
    }
    __syncthreads();
    float* ob = g_o + (size_t)(b * C_ + hd * HC_) * N_;
    for (int i = tid; i < 2048; i += 256) {
        int c = i >> 6, m = i & 63;
        ob[(size_t)c * N_ + m0 + m] = ps[m * 68 + c];
    }
}

// ============================================================
extern "C" void kernel_launch(void* const* d_in, const int* in_sizes, int n_in,
                              void* d_out, int out_size) {
    const float* q_feat = (const float*)d_in[0];
    const float* kv_feat = (const float*)d_in[1];
    const float* Wq = (const float*)d_in[2];
    const float* bq = (const float*)d_in[3];
    const float* Wk = (const float*)d_in[4];
    const float* bk = (const float*)d_in[5];
    const float* Wv = (const float*)d_in[6];
    const float* bv = (const float*)d_in[7];
    const float* Wo = (const float*)d_in[8];
    const float* bo = (const float*)d_in[9];
    const float* dw_w = (const float*)d_in[10];
    const float* dw_b = (const float*)d_in[11];
    const float* ln_w = (const float*)d_in[12];
    const float* ln_b = (const float*)d_in[13];
    const float* pw_w = (const float*)d_in[14];
    const float* rpe  = (const float*)d_in[15];
    float* out = (float*)d_out;

    float *gq, *gxs, *gk, *gv, *go;
    cudaGetSymbolAddress((void**)&gq,  g_q);
    cudaGetSymbolAddress((void**)&gxs, g_xs);
    cudaGetSymbolAddress((void**)&gk,  g_k);
    cudaGetSymbolAddress((void**)&gv,  g_v);
    cudaGetSymbolAddress((void**)&go,  g_o);

    static int smem_set = 0;
    if (!smem_set) {
        cudaFuncSetAttribute(flash_kernel,
                             cudaFuncAttributeMaxDynamicSharedMemorySize, FL_SMEM);
        smem_set = 1;
    }

    dim3 gemm_grid(N_ / 64, C_ / 64, B_);
    dim3 kv_grid(N_ / 64, C_ / 64, B_ * 2);

    gemm_proj<<<gemm_grid, 128>>>(Wq, bq, q_feat, gq);
    offset_kernel<<<(BG_ * N_ + 255) / 256, 256>>>(dw_w, dw_b, ln_w, ln_b, pw_w);
    sample_kernel<<<BG_ * N_, GC_>>>(kv_feat);
    gemm_kv<<<kv_grid, 128>>>(Wk, bk, Wv, bv, gxs, gk, gv);
    flash_kernel<<<dim3(N_ / 64, B_ * NH_), 256, FL_SMEM>>>(rpe);
    gemm_proj<<<gemm_grid, 128>>>(Wo, bo, go, out);
}

// round 12
// speedup vs baseline: 1.3807x; 1.1810x over previous
#include <cuda_runtime.h>
#include <math.h>

#define B_   4
#define C_   256
#define H_   32
#define W_   32
#define N_   1024
#define NH_  8
#define HC_  32
#define NG_  4
#define GC_  64
#define BG_  16
#define SCALE_ 0.17677669529663687f   /* 32^-0.5 */
#define EPS_  1e-5f

// ---- scratch (device globals; no allocations allowed) ----
__device__ float g_q  [B_*C_*N_];
__device__ float g_pos[BG_*N_*2];
__device__ float g_xs [B_*C_*N_];
__device__ float g_k  [B_*C_*N_];
__device__ float g_v  [B_*C_*N_];
__device__ float g_o  [B_*C_*N_];

// ---- tf32 mma helpers (3xTF32 error-compensated path) ----
__device__ __forceinline__ unsigned cvt_tf32(float x) {
    unsigned r; asm("cvt.rna.tf32.f32 %0, %1;" : "=r"(r) : "f"(x)); return r;
}
__device__ __forceinline__ void split_tf32(float x, unsigned& hi, unsigned& lo) {
    hi = cvt_tf32(x);
    lo = cvt_tf32(x - __uint_as_float(hi));
}
__device__ __forceinline__ void mma_tf32(float* d, const unsigned* a, const unsigned* b) {
    asm("mma.sync.aligned.m16n8k8.row.col.f32.tf32.tf32.f32 "
        "{%0,%1,%2,%3}, {%4,%5,%6,%7}, {%8,%9}, {%0,%1,%2,%3};"
        : "+f"(d[0]), "+f"(d[1]), "+f"(d[2]), "+f"(d[3])
        : "r"(a[0]), "r"(a[1]), "r"(a[2]), "r"(a[3]), "r"(b[0]), "r"(b[1]));
}

// ============================================================
// Projection GEMM via 3xTF32 tensor mma.
// Y[o,p] = sum_i W[o,i]*X[i,p] + bias[o]
// Block: 64(o) x 64(p), 128 threads = 4 warps, warp tile 32x32.
// ============================================================
__device__ __forceinline__ void gemm_tile_tf32(
        const float* __restrict__ Wt, const float* __restrict__ bias,
        const float* __restrict__ Xb, float* __restrict__ Yb,
        int p0, int o0, float (*Ws)[72], float (*Xs)[72]) {
    int tid = threadIdx.x;
    int lane = tid & 31, wid = tid >> 5;
    int gid = lane >> 2, tig = lane & 3;
    int wm0 = (wid >> 1) << 5;
    int wn0 = (wid & 1) << 5;

    float acc[2][4][4] = {};

    for (int kt = 0; kt < C_; kt += 16) {
        {
            int o = tid >> 1, kq = (tid & 1) << 3;
            const float* wp = &Wt[(size_t)(o0 + o) * C_ + kt + kq];
            float4 wa = *(const float4*)wp;
            float4 wb = *(const float4*)(wp + 4);
            Ws[kq + 0][o] = wa.x; Ws[kq + 1][o] = wa.y;
            Ws[kq + 2][o] = wa.z; Ws[kq + 3][o] = wa.w;
            Ws[kq + 4][o] = wb.x; Ws[kq + 5][o] = wb.y;
            Ws[kq + 6][o] = wb.z; Ws[kq + 7][o] = wb.w;
        }
#pragma unroll
        for (int it = 0; it < 2; it++) {
            int i4 = tid + (it << 7);
            int k = i4 >> 4, p = (i4 & 15) << 2;
            *(float4*)&Xs[k][p] = *(const float4*)&Xb[(size_t)(kt + k) * N_ + p0 + p];
        }
        __syncthreads();

#pragma unroll
        for (int ks = 0; ks < 16; ks += 8) {
            unsigned ah[2][4], al[2][4], bh[4][2], bl[4][2];
#pragma unroll
            for (int mi = 0; mi < 2; mi++) {
                int r = wm0 + (mi << 4) + gid;
                split_tf32(Ws[ks + tig][r],       ah[mi][0], al[mi][0]);
                split_tf32(Ws[ks + tig][r + 8],   ah[mi][1], al[mi][1]);
                split_tf32(Ws[ks + tig + 4][r],   ah[mi][2], al[mi][2]);
                split_tf32(Ws[ks + tig + 4][r + 8], ah[mi][3], al[mi][3]);
            }
#pragma unroll
            for (int ni = 0; ni < 4; ni++) {
                int cc = wn0 + (ni << 3) + gid;
                split_tf32(Xs[ks + tig][cc],     bh[ni][0], bl[ni][0]);
                split_tf32(Xs[ks + tig + 4][cc], bh[ni][1], bl[ni][1]);
            }
#pragma unroll
            for (int mi = 0; mi < 2; mi++)
#pragma unroll
                for (int ni = 0; ni < 4; ni++) {
                    mma_tf32(acc[mi][ni], ah[mi], bh[ni]);
                    mma_tf32(acc[mi][ni], ah[mi], bl[ni]);
                    mma_tf32(acc[mi][ni], al[mi], bh[ni]);
                }
        }
        __syncthreads();
    }

#pragma unroll
    for (int mi = 0; mi < 2; mi++) {
        int r = wm0 + (mi << 4) + gid;
        float bs0 = bias[o0 + r], bs1 = bias[o0 + r + 8];
#pragma unroll
        for (int ni = 0; ni < 4; ni++) {
            int cb = p0 + wn0 + (ni << 3) + (tig << 1);
            float* y0 = &Yb[(size_t)(o0 + r) * N_ + cb];
            float* y1 = &Yb[(size_t)(o0 + r + 8) * N_ + cb];
            *(float2*)y0 = make_float2(acc[mi][ni][0] + bs0, acc[mi][ni][1] + bs0);
            *(float2*)y1 = make_float2(acc[mi][ni][2] + bs1, acc[mi][ni][3] + bs1);
        }
    }
}

__global__ __launch_bounds__(128) void gemm_proj(
        const float* __restrict__ Wt, const float* __restrict__ bias,
        const float* __restrict__ X, float* __restrict__ Y) {
    __shared__ float Ws[16][72], Xs[16][72];
    int b = blockIdx.z;
    gemm_tile_tf32(Wt, bias, X + (size_t)b * C_ * N_, Y + (size_t)b * C_ * N_,
                   blockIdx.x << 6, blockIdx.y << 6, Ws, Xs);
}

__global__ __launch_bounds__(128) void gemm_kv(
        const float* __restrict__ Wk, const float* __restrict__ bk,
        const float* __restrict__ Wv, const float* __restrict__ bv,
        const float* __restrict__ X, float* __restrict__ Yk, float* __restrict__ Yv) {
    __shared__ float Ws[16][72], Xs[16][72];
    int z = blockIdx.z;
    int b = z >> 1, sel = z & 1;
    gemm_tile_tf32(sel ? Wv : Wk, sel ? bv : bk,
                   X + (size_t)b * C_ * N_, (sel ? Yv : Yk) + (size_t)b * C_ * N_,
                   blockIdx.x << 6, blockIdx.y << 6, Ws, Xs);
}

// ============================================================
// Offset network: depthwise 3x3 -> LN -> GELU -> pointwise(2)
// ============================================================
__global__ void offset_kernel(const float* __restrict__ dw_w, const float* __restrict__ dw_b,
                              const float* __restrict__ ln_w, const float* __restrict__ ln_b,
                              const float* __restrict__ pw_w) {
    int idx = blockIdx.x * blockDim.x + threadIdx.x;   // bg*N + p
    if (idx >= BG_ * N_) return;
    int bg = idx >> 10, p = idx & (N_ - 1);
    int h = p >> 5, w = p & 31;
    int b = bg >> 2, g = bg & 3;
    const float* qbase = g_q + (size_t)b * C_ * N_ + (size_t)g * GC_ * N_;

    float x[GC_];
    float s1 = 0.f;
#pragma unroll
    for (int c = 0; c < GC_; c++) {
        const float* qc = qbase + c * N_;
        float t = dw_b[c];
#pragma unroll
        for (int dy = 0; dy < 3; dy++) {
            int hh = h + dy - 1;
            if (hh < 0 || hh >= H_) continue;
#pragma unroll
            for (int dx = 0; dx < 3; dx++) {
                int ww = w + dx - 1;
                if (ww < 0 || ww >= W_) continue;
                t += dw_w[c * 9 + dy * 3 + dx] * qc[hh * W_ + ww];
            }
        }
        x[c] = t; s1 += t;
    }
    float mu = s1 * (1.f / GC_);
    float s2 = 0.f;
#pragma unroll
    for (int c = 0; c < GC_; c++) { float d = x[c] - mu; s2 += d * d; }
    float rinv = rsqrtf(s2 * (1.f / GC_) + EPS_);
    float off0 = 0.f, off1 = 0.f;
#pragma unroll
    for (int c = 0; c < GC_; c++) {
        float xn  = (x[c] - mu) * rinv * ln_w[c] + ln_b[c];
        float gel = 0.5f * xn * (1.f + erff(xn * 0.7071067811865476f));
        off0 += pw_w[c] * gel;          // y
        off1 += pw_w[GC_ + c] * gel;    // x
    }
    const float rng = 4.0f / 31.0f;
    float py = tanhf(off0) * rng + ((0.5f + (float)h) / 31.f) * 2.f - 1.f;
    float px = tanhf(off1) * rng + ((0.5f + (float)w) / 31.f) * 2.f - 1.f;
    g_pos[idx * 2 + 0] = py;
    g_pos[idx * 2 + 1] = px;
}

// ============================================================
// Deformable bilinear sampling of kv features
// ============================================================
__global__ void sample_kernel(const float* __restrict__ kv) {
    int blk = blockIdx.x;                 // bg*N + p
    int c = threadIdx.x;
    int bg = blk >> 10, p = blk & (N_ - 1);
    int b = bg >> 2, g = bg & 3;
    float py = g_pos[blk * 2 + 0], px = g_pos[blk * 2 + 1];
    float ix = (px + 1.f) * 15.5f;
    float iy = (py + 1.f) * 15.5f;
    float x0f = floorf(ix), y0f = floorf(iy);
    float wx1 = ix - x0f, wx0 = 1.f - wx1;
    float wy1 = iy - y0f, wy0 = 1.f - wy1;
    int x0 = (int)x0f, y0 = (int)y0f;
    const float* src = kv + ((size_t)b * C_ + g * GC_ + c) * N_;
    float acc = 0.f;
#pragma unroll
    for (int cy = 0; cy < 2; cy++) {
        int yy = y0 + cy;
        if (yy < 0 || yy >= H_) continue;
        float wy = cy ? wy1 : wy0;
#pragma unroll
        for (int cx = 0; cx < 2; cx++) {
            int xx = x0 + cx;
            if (xx < 0 || xx >= W_) continue;
            acc += wy * (cx ? wx1 : wx0) * src[yy * W_ + xx];
        }
    }
    g_xs[((size_t)b * C_ + g * GC_ + c) * N_ + p] = acc;
}

// ============================================================
// Fused flash attention on tensor cores (3xTF32 QK + PV).
// 128 threads = 4 warps; warp w owns m-rows [w*16, w*16+16).
// Per warp: QK = 4 kc-chunks x 8 n-tiles mma triples;
//           PV = 8 n-chunks x 4 c-tiles mma triples.
// Softmax per-row stats fully warp-local (quad shuffles).
// ============================================================
#define FL_KS 0
#define FL_VS 8704
#define FL_PS 17408
#define FL_TB 34816            /* 69*69*4 = 19044 -> pad 19072 */
#define FL_PY 53888
#define FL_PX 54144
#define FL_SMEM 54400

__global__ __launch_bounds__(128) void flash_kernel(const float* __restrict__ rpe) {
    extern __shared__ char sm_[];
    float* ks  = (float*)(sm_ + FL_KS);    // [32][68]  k tile (c-major)
    float* vs  = (float*)(sm_ + FL_VS);    // [32][68]  v tile (c-major)
    float* ps  = (float*)(sm_ + FL_PS);    // [64][68]  P (and final O transpose)
    float* tb  = (float*)(sm_ + FL_TB);    // [69][69]  zero-padded rpe table
    float* pyn = (float*)(sm_ + FL_PY);    // 64
    float* pxn = (float*)(sm_ + FL_PX);    // 64

    int tid = threadIdx.x;
    int lane = tid & 31, wid = tid >> 5;
    int gid = lane >> 2, tig = lane & 3;
    int wm = wid << 4;                     // warp m-offset in tile
    int bh = blockIdx.y, b = bh >> 3, hd = bh & 7;
    int m0 = blockIdx.x << 6;

    const float* qb = g_q + (size_t)(b * C_ + hd * HC_) * N_;
    const float* kb = g_k + (size_t)(b * C_ + hd * HC_) * N_;
    const float* vb = g_v + (size_t)(b * C_ + hd * HC_) * N_;
    int bg = b * NG_ + (hd >> 1);
    const float* tsrc = rpe + hd * 3969;

    // zero padded table then fill interior at [3][3]
    for (int i = tid; i < 69 * 69; i += 128) tb[i] = 0.f;
    __syncthreads();
    for (int i = tid; i < 3969; i += 128) {
        int y = i / 63, x = i - y * 63;
        tb[(y + 3) * 69 + x + 3] = tsrc[i];
    }

    // Q fragments (loop-invariant): rows m0+wm+gid(+8), cols kc*8+tig(+4)
    unsigned qhi[4][4], qlo[4][4];
#pragma unroll
    for (int kc = 0; kc < 4; kc++) {
        int c0 = (kc << 3) + tig;
        int mA = m0 + wm + gid;
        float a0 = qb[(size_t)c0 * N_ + mA] * SCALE_;
        float a1 = qb[(size_t)c0 * N_ + mA + 8] * SCALE_;
        float a2 = qb[(size_t)(c0 + 4) * N_ + mA] * SCALE_;
        float a3 = qb[(size_t)(c0 + 4) * N_ + mA + 8] * SCALE_;
        split_tf32(a0, qhi[kc][0], qlo[kc][0]);
        split_tf32(a1, qhi[kc][1], qlo[kc][1]);
        split_tf32(a2, qhi[kc][2], qlo[kc][2]);
        split_tf32(a3, qhi[kc][3], qlo[kc][3]);
    }

    int mrow = m0 + wm + gid;
    int moff0 = (mrow >> 5) * 69 + (mrow & 31);
    int moff1 = ((mrow + 8) >> 5) * 69 + ((mrow + 8) & 31);

    float runm0 = -1e30f, runm1 = -1e30f;
    float rsum0 = 0.f, rsum1 = 0.f;
    float oacc[4][4] = {};                  // 4 c-tiles, C-frag regs

    for (int nt = 0; nt < 16; nt++) {
        int n0 = nt << 6;
        __syncthreads();                    // prior PV reads of ks/vs done
        for (int i = tid; i < 512; i += 128) {
            int c = i >> 4, col = (i & 15) << 2;
            *(float4*)&ks[c * 68 + col] = *(const float4*)&kb[(size_t)c * N_ + n0 + col];
            *(float4*)&vs[c * 68 + col] = *(const float4*)&vb[(size_t)c * N_ + n0 + col];
        }
        if (tid < 64) {
            pyn[tid] = 15.5f - 15.5f * g_pos[((size_t)bg * N_ + n0 + tid) * 2 + 0];
            pxn[tid] = 15.5f - 15.5f * g_pos[((size_t)bg * N_ + n0 + tid) * 2 + 1];
        }
        __syncthreads();

        // ---- S = Q^T K (3xTF32 mma) ----
        float sacc[8][4] = {};
#pragma unroll
        for (int kc = 0; kc < 4; kc++) {
            int r0 = ((kc << 3) + tig) * 68;
            int r1 = ((kc << 3) + tig + 4) * 68;
#pragma unroll
            for (int j = 0; j < 8; j++) {
                int nn = (j << 3) + gid;
                unsigned b0h, b0l, b1h, b1l;
                split_tf32(ks[r0 + nn], b0h, b0l);
                split_tf32(ks[r1 + nn], b1h, b1l);
                unsigned bh2[2] = {b0h, b1h}, bl2[2] = {b0l, b1l};
                mma_tf32(sacc[j], qhi[kc], bh2);
                mma_tf32(sacc[j], qhi[kc], bl2);
                mma_tf32(sacc[j], qlo[kc], bh2);
            }
        }

        // ---- + rpe bias (fractions constant per n; pad-3 table) ----
#pragma unroll
        for (int j = 0; j < 8; j++) {
#pragma unroll
            for (int e = 0; e < 2; e++) {
                int nn = (j << 3) + (tig << 1) + e;
                float biy = pyn[nn], bix = pxn[nn];
                float fy = floorf(biy), fx = floorf(bix);
                float wy1 = biy - fy, wx1 = bix - fx;
                float wy0 = 1.f - wy1, wx0 = 1.f - wx1;
                int idxb = ((int)fy + 3) * 69 + (int)fx + 3;
                float w00 = wy0 * wx0, w01 = wy0 * wx1;
                float w10 = wy1 * wx0, w11 = wy1 * wx1;
                int ia = idxb + moff0;
                sacc[j][e] += w00 * tb[ia] + w01 * tb[ia + 1]
                            + w10 * tb[ia + 69] + w11 * tb[ia + 70];
                int ib = idxb + moff1;
                sacc[j][2 + e] += w00 * tb[ib] + w01 * tb[ib + 1]
                                + w10 * tb[ib + 69] + w11 * tb[ib + 70];
            }
        }

        // ---- online softmax (rows gid and gid+8; quad shuffles) ----
        float tm0 = -1e30f, tm1 = -1e30f;
#pragma unroll
        for (int j = 0; j < 8; j++) {
            tm0 = fmaxf(tm0, fmaxf(sacc[j][0], sacc[j][1]));
            tm1 = fmaxf(tm1, fmaxf(sacc[j][2], sacc[j][3]));
        }
        tm0 = fmaxf(tm0, __shfl_xor_sync(0xffffffffu, tm0, 1));
        tm0 = fmaxf(tm0, __shfl_xor_sync(0xffffffffu, tm0, 2));
        tm1 = fmaxf(tm1, __shfl_xor_sync(0xffffffffu, tm1, 1));
        tm1 = fmaxf(tm1, __shfl_xor_sync(0xffffffffu, tm1, 2));
        float nm0 = fmaxf(runm0, tm0), nm1 = fmaxf(runm1, tm1);
        float corr0 = __expf(runm0 - nm0), corr1 = __expf(runm1 - nm1);
        runm0 = nm0; runm1 = nm1;
        float lsum0 = 0.f, lsum1 = 0.f;
        int pr0 = (wm + gid) * 68 + (tig << 1);
        int pr1 = (wm + gid + 8) * 68 + (tig << 1);
#pragma unroll
        for (int j = 0; j < 8; j++) {
            float p0 = __expf(sacc[j][0] - nm0);
            float p1 = __expf(sacc[j][1] - nm0);
            float p2 = __expf(sacc[j][2] - nm1);
            float p3 = __expf(sacc[j][3] - nm1);
            lsum0 += p0 + p1; lsum1 += p2 + p3;
            *(float2*)&ps[pr0 + (j << 3)] = make_float2(p0, p1);
            *(float2*)&ps[pr1 + (j << 3)] = make_float2(p2, p3);
        }
        rsum0 = rsum0 * corr0 + lsum0;
        rsum1 = rsum1 * corr1 + lsum1;
#pragma unroll
        for (int ct = 0; ct < 4; ct++) {
            oacc[ct][0] *= corr0; oacc[ct][1] *= corr0;
            oacc[ct][2] *= corr1; oacc[ct][3] *= corr1;
        }
        __syncwarp();   // P rows are warp-private; warp-level sync suffices

        // ---- O += P V (3xTF32 mma; A=P from smem, B=V) ----
#pragma unroll
        for (int kc = 0; kc < 8; kc++) {
            int kcol = (kc << 3) + tig;
            unsigned ah[4], al[4];
            split_tf32(ps[(wm + gid) * 68 + kcol],         ah[0], al[0]);
            split_tf32(ps[(wm + gid + 8) * 68 + kcol],     ah[1], al[1]);
            split_tf32(ps[(wm + gid) * 68 + kcol + 4],     ah[2], al[2]);
            split_tf32(ps[(wm + gid + 8) * 68 + kcol + 4], ah[3], al[3]);
#pragma unroll
            for (int ct = 0; ct < 4; ct++) {
                int vrow = ((ct << 3) + gid) * 68 + (kc << 3) + tig;
                unsigned b0h, b0l, b1h, b1l;
                split_tf32(vs[vrow],     b0h, b0l);
                split_tf32(vs[vrow + 4], b1h, b1l);
                unsigned bh2[2] = {b0h, b1h}, bl2[2] = {b0l, b1l};
                mma_tf32(oacc[ct], ah, bh2);
                mma_tf32(oacc[ct], ah, bl2);
                mma_tf32(oacc[ct], al, bh2);
            }
        }
    }

    // final row sums (quad reduce), normalize, write via smem transpose
    rsum0 += __shfl_xor_sync(0xffffffffu, rsum0, 1);
    rsum0 += __shfl_xor_sync(0xffffffffu, rsum0, 2);
    rsum1 += __shfl_xor_sync(0xffffffffu, rsum1, 1);
    rsum1 += __shfl_xor_sync(0xffffffffu, rsum1, 2);
    float inv0 = 1.f / rsum0, inv1 = 1.f / rsum1;

    __syncthreads();   // everyone done reading ps as P
#pragma unroll
    for (int ct = 0; ct < 4; ct++) {
        int cc = (ct << 3) + (tig << 1);
        *(float2*)&ps[(wm + gid) * 68 + cc] =
            make_float2(oacc[ct][0] * inv0, oacc[ct][1] * inv0);
        *(float2*)&ps[(wm + gid + 8) * 68 + cc] =
            make_float2(oacc[ct][2] * inv1, oacc[ct][3] * inv1);
    }
    __syncthreads();
    float* ob = g_o + (size_t)(b * C_ + hd * HC_) * N_;
    for (int i = tid; i < 2048; i += 128) {
        int c = i >> 6, m = i & 63;
        ob[(size_t)c * N_ + m0 + m] = ps[m * 68 + c];
    }
}

// ============================================================
extern "C" void kernel_launch(void* const* d_in, const int* in_sizes, int n_in,
                              void* d_out, int out_size) {
    const float* q_feat = (const float*)d_in[0];
    const float* kv_feat = (const float*)d_in[1];
    const float* Wq = (const float*)d_in[2];
    const float* bq = (const float*)d_in[3];
    const float* Wk = (const float*)d_in[4];
    const float* bk = (const float*)d_in[5];
    const float* Wv = (const float*)d_in[6];
    const float* bv = (const float*)d_in[7];
    const float* Wo = (const float*)d_in[8];
    const float* bo = (const float*)d_in[9];
    const float* dw_w = (const float*)d_in[10];
    const float* dw_b = (const float*)d_in[11];
    const float* ln_w = (const float*)d_in[12];
    const float* ln_b = (const float*)d_in[13];
    const float* pw_w = (const float*)d_in[14];
    const float* rpe  = (const float*)d_in[15];
    float* out = (float*)d_out;

    float *gq, *gxs, *gk, *gv, *go;
    cudaGetSymbolAddress((void**)&gq,  g_q);
    cudaGetSymbolAddress((void**)&gxs, g_xs);
    cudaGetSymbolAddress((void**)&gk,  g_k);
    cudaGetSymbolAddress((void**)&gv,  g_v);
    cudaGetSymbolAddress((void**)&go,  g_o);

    static int smem_set = 0;
    if (!smem_set) {
        cudaFuncSetAttribute(flash_kernel,
                             cudaFuncAttributeMaxDynamicSharedMemorySize, FL_SMEM);
        smem_set = 1;
    }

    dim3 gemm_grid(N_ / 64, C_ / 64, B_);
    dim3 kv_grid(N_ / 64, C_ / 64, B_ * 2);

    gemm_proj<<<gemm_grid, 128>>>(Wq, bq, q_feat, gq);
    offset_kernel<<<(BG_ * N_ + 255) / 256, 256>>>(dw_w, dw_b, ln_w, ln_b, pw_w);
    sample_kernel<<<BG_ * N_, GC_>>>(kv_feat);
    gemm_kv<<<kv_grid, 128>>>(Wk, bk, Wv, bv, gxs, gk, gv);
    flash_kernel<<<dim3(N_ / 64, B_ * NH_), 128, FL_SMEM>>>(rpe);
    gemm_proj<<<gemm_grid, 128>>>(Wo, bo, go, out);
}